// round 1
// baseline (speedup 1.0000x reference)
#include <cuda_runtime.h>
#include <math.h>

// Problem constants
#define B_SZ   64
#define T_SZ   512
#define D_IN   968
#define HID    128
#define G3     384            // 3*HID
#define MROWS  (B_SZ * T_SZ)  // 32768

// ---------------- scratch (no cudaMalloc allowed) ----------------
// xp[dir][b][t][g] : input projections for both directions
__device__ float g_xp[2u * MROWS * G3];   // ~100.7 MB

// =================================================================
// Kernel 1: fused input-projection GEMM (fp32)
//   out[m][n] = dot(x[m, :], W[n, :]) + bias[n]
//   n in [0,384) -> forward weights, [384,768) -> backward
//   M = 32768, N = 768, K = 968
// =================================================================
#define BM 64
#define BN 64
#define BK 8

__global__ __launch_bounds__(256) void gemm_xproj(
    const float* __restrict__ x,       // [MROWS, 968]
    const float* __restrict__ w_f,     // [384, 968]
    const float* __restrict__ w_b,     // [384, 968]
    const float* __restrict__ bias_f,  // [384]
    const float* __restrict__ bias_b)  // [384]
{
    __shared__ float As[BK][68];   // k-major, padded (68*4B = 272 = 17*16, fp4-aligned rows)
    __shared__ float Bs[BK][68];

    const int tid = threadIdx.x;
    const int tx  = tid & 15;
    const int ty  = tid >> 4;
    const int m0  = blockIdx.y * BM;
    const int n0  = blockIdx.x * BN;
    const int dir = (n0 >= G3) ? 1 : 0;
    const int gbase = n0 - dir * G3;

    const float* __restrict__ wsrc = dir ? w_b : w_f;
    const float* __restrict__ bsrc = dir ? bias_b : bias_f;

    // loader mapping: 512 elems per tile, 256 threads -> 2 each
    const int lr = tid >> 3;   // 0..31
    const int lc = tid & 7;    // 0..7  (k within tile)

    float acc[4][4];
#pragma unroll
    for (int i = 0; i < 4; i++)
#pragma unroll
        for (int j = 0; j < 4; j++) acc[i][j] = 0.f;

    const float* xA0 = x + (size_t)(m0 + lr) * D_IN;
    const float* xA1 = x + (size_t)(m0 + lr + 32) * D_IN;
    const float* wB0 = wsrc + (size_t)(gbase + lr) * D_IN;
    const float* wB1 = wsrc + (size_t)(gbase + lr + 32) * D_IN;

    for (int kt = 0; kt < D_IN; kt += BK) {
        As[lc][lr]      = xA0[kt + lc];
        As[lc][lr + 32] = xA1[kt + lc];
        Bs[lc][lr]      = wB0[kt + lc];
        Bs[lc][lr + 32] = wB1[kt + lc];
        __syncthreads();
#pragma unroll
        for (int k = 0; k < BK; k++) {
            float4 a = *(const float4*)&As[k][ty * 4];
            float4 b = *(const float4*)&Bs[k][tx * 4];
            acc[0][0] = fmaf(a.x, b.x, acc[0][0]);
            acc[0][1] = fmaf(a.x, b.y, acc[0][1]);
            acc[0][2] = fmaf(a.x, b.z, acc[0][2]);
            acc[0][3] = fmaf(a.x, b.w, acc[0][3]);
            acc[1][0] = fmaf(a.y, b.x, acc[1][0]);
            acc[1][1] = fmaf(a.y, b.y, acc[1][1]);
            acc[1][2] = fmaf(a.y, b.z, acc[1][2]);
            acc[1][3] = fmaf(a.y, b.w, acc[1][3]);
            acc[2][0] = fmaf(a.z, b.x, acc[2][0]);
            acc[2][1] = fmaf(a.z, b.y, acc[2][1]);
            acc[2][2] = fmaf(a.z, b.z, acc[2][2]);
            acc[2][3] = fmaf(a.z, b.w, acc[2][3]);
            acc[3][0] = fmaf(a.w, b.x, acc[3][0]);
            acc[3][1] = fmaf(a.w, b.y, acc[3][1]);
            acc[3][2] = fmaf(a.w, b.z, acc[3][2]);
            acc[3][3] = fmaf(a.w, b.w, acc[3][3]);
        }
        __syncthreads();
    }

    // epilogue: add bias, write to g_xp[dir][m][g]
    const int gcol = gbase + tx * 4;
    float4 bias4 = *(const float4*)&bsrc[gcol];
#pragma unroll
    for (int i = 0; i < 4; i++) {
        int m = m0 + ty * 4 + i;
        float4 o;
        o.x = acc[i][0] + bias4.x;
        o.y = acc[i][1] + bias4.y;
        o.z = acc[i][2] + bias4.z;
        o.w = acc[i][3] + bias4.w;
        *(float4*)&g_xp[((size_t)dir * MROWS + m) * G3 + gcol] = o;
    }
}

// =================================================================
// Kernel 2: GRU recurrent scan. One CTA per (batch, direction).
//   384 threads; w_hh staged k-major in dynamic smem (196 KB).
//   Writes pre-LN hidden states straight into d_out[b][t][dir*128 + i].
// =================================================================
__global__ __launch_bounds__(384) void gru_scan(
    const float* __restrict__ w_hh_f,  // [384,128]
    const float* __restrict__ w_hh_b,
    const float* __restrict__ b_hh_f,  // [384]
    const float* __restrict__ b_hh_b,
    float* __restrict__ out)           // [B, T, 256]
{
    extern __shared__ float smem[];
    float4* w4  = (float4*)smem;       // [32][384] float4  (k-major)
    float*  h_s = smem + 4 * 32 * 384; // [128]
    float*  s1  = h_s + 128;           // [384]  gh(+gi) per gate-col
    float*  s2  = s1 + 384;            // [128]  raw gi_n
    float*  bb  = s2 + 128;            // [384]  b_hh

    const int j   = threadIdx.x;        // 0..383
    const int dir = blockIdx.x & 1;
    const int b   = blockIdx.x >> 1;

    const float* __restrict__ w  = dir ? w_hh_b : w_hh_f;
    const float* __restrict__ bh = dir ? b_hh_b : b_hh_f;

    // stage weights transposed: w4[kk][j] = w[j][4kk..4kk+3]
#pragma unroll
    for (int kk = 0; kk < 32; kk++)
        w4[kk * 384 + j] = *(const float4*)&w[(size_t)j * HID + kk * 4];
    bb[j] = bh[j];
    if (j < HID) h_s[j] = 0.f;
    __syncthreads();

    const float4* h4 = (const float4*)h_s;
    const float* xp_base  = g_xp + ((size_t)dir * MROWS + (size_t)b * T_SZ) * G3;
    float*       out_base = out + (size_t)b * T_SZ * 256 + dir * HID;

    for (int s = 0; s < T_SZ; s++) {
        const int t = dir ? (T_SZ - 1 - s) : s;
        const float gi = xp_base[(size_t)t * G3 + j];

        float acc = 0.f;
#pragma unroll
        for (int kk = 0; kk < 32; kk++) {
            float4 wv = w4[kk * 384 + j];
            float4 hv = h4[kk];
            acc = fmaf(wv.x, hv.x, acc);
            acc = fmaf(wv.y, hv.y, acc);
            acc = fmaf(wv.z, hv.z, acc);
            acc = fmaf(wv.w, hv.w, acc);
        }
        acc += bb[j];
        if (j < 256) {
            s1[j] = acc + gi;          // r/z gates: gi + gh fused
        } else {
            s1[j] = acc;               // n gate: keep gh raw (needs r * gh_n)
            s2[j - 256] = gi;
        }
        __syncthreads();

        if (j < HID) {
            const float r = 1.f / (1.f + __expf(-s1[j]));
            const float z = 1.f / (1.f + __expf(-s1[HID + j]));
            const float n = tanhf(fmaf(r, s1[2 * HID + j], s2[j]));
            const float hn = (1.f - z) * n + z * h_s[j];
            h_s[j] = hn;
            out_base[(size_t)t * 256 + j] = hn;
        }
        __syncthreads();
    }
}

// =================================================================
// Kernel 3: LayerNorm (unbiased std, ddof=1, clamp 1e-6), in place.
//   One block per (b,t) row of 256.
// =================================================================
__global__ __launch_bounds__(256) void layernorm_rows(
    float* __restrict__ out,
    const float* __restrict__ ln_w,
    const float* __restrict__ ln_b)
{
    const size_t row = blockIdx.x;
    const int c = threadIdx.x;
    float* p = out + row * 256;
    const float v = p[c];

    float s = v, ss = v * v;
#pragma unroll
    for (int o = 16; o > 0; o >>= 1) {
        s  += __shfl_xor_sync(0xffffffffu, s, o);
        ss += __shfl_xor_sync(0xffffffffu, ss, o);
    }
    __shared__ float rs[8], rss[8];
    const int wid = c >> 5, lid = c & 31;
    if (lid == 0) { rs[wid] = s; rss[wid] = ss; }
    __syncthreads();
    if (c < 32) {
        s  = (lid < 8) ? rs[lid]  : 0.f;
        ss = (lid < 8) ? rss[lid] : 0.f;
#pragma unroll
        for (int o = 4; o > 0; o >>= 1) {
            s  += __shfl_xor_sync(0xffffffffu, s, o);
            ss += __shfl_xor_sync(0xffffffffu, ss, o);
        }
        if (lid == 0) { rs[0] = s; rss[0] = ss; }
    }
    __syncthreads();
    s = rs[0]; ss = rss[0];

    const float mu  = s * (1.f / 256.f);
    float var = (ss - 256.f * mu * mu) * (1.f / 255.f);
    float sig = sqrtf(fmaxf(var, 0.f));
    sig = fmaxf(sig, 1e-6f);
    p[c] = (v - mu) / sig * ln_w[c] + ln_b[c];
}

// =================================================================
// launch
// =================================================================
extern "C" void kernel_launch(void* const* d_in, const int* in_sizes, int n_in,
                              void* d_out, int out_size)
{
    const float* x      = (const float*)d_in[0];
    const float* w_ih_f = (const float*)d_in[1];
    const float* w_hh_f = (const float*)d_in[2];
    const float* b_ih_f = (const float*)d_in[3];
    const float* b_hh_f = (const float*)d_in[4];
    const float* w_ih_b = (const float*)d_in[5];
    const float* w_hh_b = (const float*)d_in[6];
    const float* b_ih_b = (const float*)d_in[7];
    const float* b_hh_b = (const float*)d_in[8];
    const float* ln_w   = (const float*)d_in[9];
    const float* ln_b   = (const float*)d_in[10];
    float* out = (float*)d_out;

    static bool scan_smem_set = []() {
        cudaFuncSetAttribute(gru_scan, cudaFuncAttributeMaxDynamicSharedMemorySize,
                             (4 * 32 * 384 + 128 + 384 + 128 + 384) * (int)sizeof(float));
        return true;
    }();
    (void)scan_smem_set;

    // 1) input projections (both directions in one GEMM grid)
    dim3 ggrid(2 * G3 / BN, MROWS / BM);  // (12, 512)
    gemm_xproj<<<ggrid, 256>>>(x, w_ih_f, w_ih_b, b_ih_f, b_ih_b);

    // 2) recurrent scan: 128 CTAs = 64 batch x 2 directions
    const int scan_smem = (4 * 32 * 384 + 128 + 384 + 128 + 384) * (int)sizeof(float);
    gru_scan<<<B_SZ * 2, 384, scan_smem>>>(w_hh_f, w_hh_b, b_hh_f, b_hh_b, out);

    // 3) layernorm in place
    layernorm_rows<<<MROWS, 256>>>(out, ln_w, ln_b);
}

// round 3
// speedup vs baseline: 1.8045x; 1.8045x over previous
#include <cuda_runtime.h>
#include <cuda_bf16.h>
#include <math.h>
#include <stdint.h>

// ---------------- problem constants ----------------
#define B_SZ   64
#define T_SZ   512
#define D_IN   968
#define HID    128
#define G3     384
#define MROWS  (B_SZ * T_SZ)      // 32768
#define KPAD   1024
#define KCAT   (3 * KPAD)         // 3072: x=[hi|lo|hi] vs w=[hi|hi|lo]
#define NTOT   768

// ---------------- scratch ----------------
__device__ float g_xp[2u * MROWS * G3];
__device__ __nv_bfloat16 g_abf[(size_t)MROWS * KCAT];
__device__ __nv_bfloat16 g_wbf[(size_t)NTOT * KCAT];

// ---------------- helpers ----------------
__device__ __forceinline__ uint32_t smem_u32(const void* p) {
    uint32_t a;
    asm("{ .reg .u64 t; cvta.to.shared.u64 t, %1; cvt.u32.u64 %0, t; }" : "=r"(a) : "l"(p));
    return a;
}
__device__ __forceinline__ void cp16(uint32_t dst, const void* src) {
    asm volatile("cp.async.cg.shared.global [%0], [%1], 16;" :: "r"(dst), "l"(src));
}
__device__ __forceinline__ void cp_commit() {
    asm volatile("cp.async.commit_group;" ::: "memory");
}
__device__ __forceinline__ void cp_wait2() {
    asm volatile("cp.async.wait_group 2;" ::: "memory");
}
__device__ __forceinline__ void ldmx4(uint32_t* r, uint32_t a) {
    asm volatile("ldmatrix.sync.aligned.m8n8.x4.shared.b16 {%0,%1,%2,%3}, [%4];"
                 : "=r"(r[0]), "=r"(r[1]), "=r"(r[2]), "=r"(r[3]) : "r"(a));
}
__device__ __forceinline__ void mma_bf16(float* c, const uint32_t* a, const uint32_t* b) {
    asm volatile("mma.sync.aligned.m16n8k16.row.col.f32.bf16.bf16.f32 "
                 "{%0,%1,%2,%3}, {%4,%5,%6,%7}, {%8,%9}, {%0,%1,%2,%3};"
                 : "+f"(c[0]), "+f"(c[1]), "+f"(c[2]), "+f"(c[3])
                 : "r"(a[0]), "r"(a[1]), "r"(a[2]), "r"(a[3]), "r"(b[0]), "r"(b[1]));
}
__device__ __forceinline__ unsigned long long fma2(unsigned long long a,
                                                   unsigned long long b,
                                                   unsigned long long c) {
    unsigned long long d;
    asm("fma.rn.f32x2 %0, %1, %2, %3;" : "=l"(d) : "l"(a), "l"(b), "l"(c));
    return d;
}

// =================================================================
// Kernel 0a/0b: fp32 -> split-bf16 (K padded to 1024, 3-term concat)
// =================================================================
__global__ __launch_bounds__(256) void conv_x(const float* __restrict__ x) {
    const int m = blockIdx.x;
    const float* src = x + (size_t)m * D_IN;
    __nv_bfloat16* dst = g_abf + (size_t)m * KCAT;
    for (int k = threadIdx.x; k < KPAD; k += 256) {
        float v = (k < D_IN) ? src[k] : 0.f;
        __nv_bfloat16 hi = __float2bfloat16(v);
        __nv_bfloat16 lo = __float2bfloat16(v - __bfloat162float(hi));
        dst[k]            = hi;
        dst[KPAD + k]     = lo;
        dst[2 * KPAD + k] = hi;
    }
}
__global__ __launch_bounds__(256) void conv_w(const float* __restrict__ w_f,
                                              const float* __restrict__ w_b) {
    const int n = blockIdx.x;
    const float* src = (n < G3) ? (w_f + (size_t)n * D_IN) : (w_b + (size_t)(n - G3) * D_IN);
    __nv_bfloat16* dst = g_wbf + (size_t)n * KCAT;
    for (int k = threadIdx.x; k < KPAD; k += 256) {
        float v = (k < D_IN) ? src[k] : 0.f;
        __nv_bfloat16 hi = __float2bfloat16(v);
        __nv_bfloat16 lo = __float2bfloat16(v - __bfloat162float(hi));
        dst[k]            = hi;
        dst[KPAD + k]     = hi;
        dst[2 * KPAD + k] = lo;
    }
}

// =================================================================
// Kernel 1: HMMA bf16 GEMM.  M=32768, N=768, K=3072.
//   CTA 128x128x32, 8 warps (warp tile 64x32), 3-stage cp.async pipe.
//   smem rows padded to 80B -> conflict-free ldmatrix without swizzle.
// =================================================================
#define BK      32
#define ROWB    80                   // 64B data + 16B pad
#define ATILE   (128 * ROWB)         // 10240
#define STAGEB  (2 * ATILE)          // A + B
#define NSTG    (KCAT / BK)          // 96
#define GEMM_SMEM (3 * STAGEB)       // 61440

__global__ __launch_bounds__(256, 2) void gemm_mma(const float* __restrict__ bias_f,
                                                   const float* __restrict__ bias_b) {
    extern __shared__ char smem[];
    const uint32_t sb = smem_u32(smem);
    const int tid  = threadIdx.x;
    const int wid  = tid >> 5;
    const int lane = tid & 31;
    const int wrow = wid >> 2;        // 0..1  (64 rows each)
    const int wcol = wid & 3;         // 0..3  (32 cols each)

    const int m0 = blockIdx.y * 128;
    const int n0 = blockIdx.x * 128;

    const __nv_bfloat16* Ag = g_abf + (size_t)m0 * KCAT;
    const __nv_bfloat16* Bg = g_wbf + (size_t)n0 * KCAT;

    // loader mapping: 512 16B chunks per tile, 256 threads x 2
    const int lrow  = tid >> 1;            // 0..127
    const int lseg0 = (tid & 1) * 2;       // 0 or 2

    float acc[4][4][4];
#pragma unroll
    for (int i = 0; i < 4; i++)
#pragma unroll
        for (int j = 0; j < 4; j++)
#pragma unroll
            for (int q = 0; q < 4; q++) acc[i][j][q] = 0.f;

    // ---- issue helper (stage s -> buffer s%3) ----
    auto issue = [&](int s) {
        const uint32_t st = sb + (s % 3) * STAGEB;
        const size_t gk = (size_t)s * BK;
        const __nv_bfloat16* arow = Ag + (size_t)lrow * KCAT + gk;
        const __nv_bfloat16* brow = Bg + (size_t)lrow * KCAT + gk;
        cp16(st + lrow * ROWB + lseg0 * 16,        arow + lseg0 * 8);
        cp16(st + lrow * ROWB + (lseg0 + 1) * 16,  arow + (lseg0 + 1) * 8);
        cp16(st + ATILE + lrow * ROWB + lseg0 * 16,       brow + lseg0 * 8);
        cp16(st + ATILE + lrow * ROWB + (lseg0 + 1) * 16, brow + (lseg0 + 1) * 8);
    };

    issue(0); cp_commit();
    issue(1); cp_commit();

    // ldmatrix base addresses (lane-dependent parts)
    const int a_r = (lane & 15);          // row within 16
    const int a_c = (lane >> 4) * 16;     // 0 or 16 bytes (k-half of 8 elems)
    const int b_r = (lane & 7) + ((lane >> 4) << 3);  // row within 16 (two n-frags)
    const int b_c = ((lane >> 3) & 1) * 16;

    for (int s = 0; s < NSTG; s++) {
        __syncthreads();                 // protect buffer (s+2)%3 from overwrite
        if (s + 2 < NSTG) issue(s + 2);
        cp_commit();
        cp_wait2();
        __syncthreads();

        const uint32_t st = sb + (s % 3) * STAGEB;
        const uint32_t aw = st + (wrow * 64 + a_r) * ROWB + a_c;
        const uint32_t bw = st + ATILE + (wcol * 32 + b_r) * ROWB + b_c;

#pragma unroll
        for (int kh = 0; kh < 2; kh++) {
            uint32_t afr[4][4], bfr[2][4];
#pragma unroll
            for (int mf = 0; mf < 4; mf++)
                ldmx4(afr[mf], aw + mf * 16 * ROWB + kh * 32);
#pragma unroll
            for (int np = 0; np < 2; np++)
                ldmx4(bfr[np], bw + np * 16 * ROWB + kh * 32);
#pragma unroll
            for (int mf = 0; mf < 4; mf++) {
#pragma unroll
                for (int nf = 0; nf < 4; nf++) {
                    uint32_t bp[2];
                    bp[0] = bfr[nf >> 1][(nf & 1) * 2 + 0];
                    bp[1] = bfr[nf >> 1][(nf & 1) * 2 + 1];
                    mma_bf16(acc[mf][nf], afr[mf], bp);
                }
            }
        }
    }

    // ---- epilogue: add bias, write g_xp ----
    const int dir = (n0 >= G3) ? 1 : 0;
    const int gbase = n0 - dir * G3;
    const float* bias = dir ? bias_b : bias_f;

#pragma unroll
    for (int mf = 0; mf < 4; mf++) {
#pragma unroll
        for (int nf = 0; nf < 4; nf++) {
            const int g = gbase + wcol * 32 + nf * 8 + (lane & 3) * 2;
            const float bx = bias[g], by = bias[g + 1];
            const int r0 = m0 + wrow * 64 + mf * 16 + (lane >> 2);
            float* d0 = g_xp + ((size_t)dir * MROWS + r0) * G3 + g;
            float* d1 = d0 + (size_t)8 * G3;
            float2 v0 = make_float2(acc[mf][nf][0] + bx, acc[mf][nf][1] + by);
            float2 v1 = make_float2(acc[mf][nf][2] + bx, acc[mf][nf][3] + by);
            *(float2*)d0 = v0;
            *(float2*)d1 = v1;
        }
    }
}

// =================================================================
// Kernel 2: GRU scan — weights in registers, packed f32x2 FMA.
//   One CTA per (batch, direction); thread j owns gate-row j.
// =================================================================
__global__ __launch_bounds__(384, 1) void gru_scan(
    const float* __restrict__ w_hh_f, const float* __restrict__ w_hh_b,
    const float* __restrict__ b_hh_f, const float* __restrict__ b_hh_b,
    float* __restrict__ out)
{
    __shared__ float h_s[128];
    __shared__ float s1[384];
    __shared__ float s2[128];

    const int j   = threadIdx.x;
    const int dir = blockIdx.x & 1;
    const int b   = blockIdx.x >> 1;

    const float* __restrict__ w  = dir ? w_hh_b : w_hh_f;
    const float* __restrict__ bh = dir ? b_hh_b : b_hh_f;

    // weights row j -> 64 packed f32x2 registers
    unsigned long long wp[64];
    const float4* wrow = (const float4*)(w + (size_t)j * HID);
#pragma unroll
    for (int q = 0; q < 32; q++) {
        float4 v = wrow[q];
        float2 p0 = make_float2(v.x, v.y);
        float2 p1 = make_float2(v.z, v.w);
        wp[2 * q]     = *(unsigned long long*)&p0;
        wp[2 * q + 1] = *(unsigned long long*)&p1;
    }
    const float bj = bh[j];
    if (j < HID) h_s[j] = 0.f;
    __syncthreads();

    const float* xp_base  = g_xp + ((size_t)dir * MROWS + (size_t)b * T_SZ) * G3;
    float*       out_base = out + (size_t)b * T_SZ * 256 + dir * HID;
    const float4* h4 = (const float4*)h_s;

    for (int s = 0; s < T_SZ; s++) {
        const int t = dir ? (T_SZ - 1 - s) : s;
        const float gi = xp_base[(size_t)t * G3 + j];

        unsigned long long acc2 = 0ull;
#pragma unroll
        for (int q = 0; q < 32; q++) {
            float4 hv = h4[q];
            float2 p0 = make_float2(hv.x, hv.y);
            float2 p1 = make_float2(hv.z, hv.w);
            acc2 = fma2(wp[2 * q],     *(unsigned long long*)&p0, acc2);
            acc2 = fma2(wp[2 * q + 1], *(unsigned long long*)&p1, acc2);
        }
        float2 ap = *(float2*)&acc2;
        const float acc = ap.x + ap.y + bj;

        if (j < 256) {
            s1[j] = acc + gi;
        } else {
            s1[j] = acc;
            s2[j - 256] = gi;
        }
        __syncthreads();

        if (j < HID) {
            const float r = 1.f / (1.f + __expf(-s1[j]));
            const float z = 1.f / (1.f + __expf(-s1[HID + j]));
            const float n = tanhf(fmaf(r, s1[2 * HID + j], s2[j]));
            const float hn = (1.f - z) * n + z * h_s[j];
            h_s[j] = hn;
            out_base[(size_t)t * 256 + j] = hn;
        }
        __syncthreads();
    }
}

// =================================================================
// Kernel 3: LayerNorm (ddof=1 std, clamp 1e-6), in place
// =================================================================
__global__ __launch_bounds__(256) void layernorm_rows(
    float* __restrict__ out, const float* __restrict__ ln_w, const float* __restrict__ ln_b)
{
    const size_t row = blockIdx.x;
    const int c = threadIdx.x;
    float* p = out + row * 256;
    const float v = p[c];

    float s = v, ss = v * v;
#pragma unroll
    for (int o = 16; o > 0; o >>= 1) {
        s  += __shfl_xor_sync(0xffffffffu, s, o);
        ss += __shfl_xor_sync(0xffffffffu, ss, o);
    }
    __shared__ float rs[8], rss[8];
    const int wid = c >> 5, lid = c & 31;
    if (lid == 0) { rs[wid] = s; rss[wid] = ss; }
    __syncthreads();
    if (c < 32) {
        s  = (lid < 8) ? rs[lid]  : 0.f;
        ss = (lid < 8) ? rss[lid] : 0.f;
#pragma unroll
        for (int o = 4; o > 0; o >>= 1) {
            s  += __shfl_xor_sync(0xffffffffu, s, o);
            ss += __shfl_xor_sync(0xffffffffu, ss, o);
        }
        if (lid == 0) { rs[0] = s; rss[0] = ss; }
    }
    __syncthreads();
    s = rs[0]; ss = rss[0];

    const float mu  = s * (1.f / 256.f);
    float var = (ss - 256.f * mu * mu) * (1.f / 255.f);
    float sig = sqrtf(fmaxf(var, 0.f));
    sig = fmaxf(sig, 1e-6f);
    p[c] = (v - mu) / sig * ln_w[c] + ln_b[c];
}

// =================================================================
// launch
// =================================================================
extern "C" void kernel_launch(void* const* d_in, const int* in_sizes, int n_in,
                              void* d_out, int out_size)
{
    const float* x      = (const float*)d_in[0];
    const float* w_ih_f = (const float*)d_in[1];
    const float* w_hh_f = (const float*)d_in[2];
    const float* b_ih_f = (const float*)d_in[3];
    const float* b_hh_f = (const float*)d_in[4];
    const float* w_ih_b = (const float*)d_in[5];
    const float* w_hh_b = (const float*)d_in[6];
    const float* b_ih_b = (const float*)d_in[7];
    const float* b_hh_b = (const float*)d_in[8];
    const float* ln_w   = (const float*)d_in[9];
    const float* ln_b   = (const float*)d_in[10];
    float* out = (float*)d_out;

    static bool attrs_set = []() {
        cudaFuncSetAttribute(gemm_mma, cudaFuncAttributeMaxDynamicSharedMemorySize, GEMM_SMEM);
        return true;
    }();
    (void)attrs_set;

    conv_x<<<MROWS, 256>>>(x);
    conv_w<<<NTOT, 256>>>(w_ih_f, w_ih_b);

    dim3 ggrid(NTOT / 128, MROWS / 128);   // (6, 256)
    gemm_mma<<<ggrid, 256, GEMM_SMEM>>>(b_ih_f, b_ih_b);

    gru_scan<<<B_SZ * 2, 384>>>(w_hh_f, w_hh_b, b_hh_f, b_hh_b, out);

    layernorm_rows<<<MROWS, 256>>>(out, ln_w, ln_b);
}